// round 2
// baseline (speedup 1.0000x reference)
#include <cuda_runtime.h>

// Problem constants
constexpr int kB = 4, kT = 256, kU = 64, kD = 512, kInner = 512, kVocab = 2048;
constexpr int kEncRows = kB * kT;      // 1024
constexpr int kDecRows = kB * kU;      // 256
constexpr int kMRows   = kB * kT * kU; // 65536

// Scratch (static device globals — allocation-free per harness rules)
__device__ float g_eproj[kEncRows * kInner];                 // enc @ We + b1
__device__ float g_dproj[kDecRows * kInner];                 // dec @ Wd
__device__ float g_hidden[(size_t)kMRows * kInner];          // 134 MB tanh(...)

// ---------------------------------------------------------------------------
// K1: fused projection GEMM. Rows [0,1024) = enc @ W1[:512] + b1,
//     rows [1024,1280) = dec @ W1[512:]. 64x64 tiles, 256 threads, 4x4/thread.
// ---------------------------------------------------------------------------
__global__ void proj_kernel(const float* __restrict__ enc, const float* __restrict__ dec,
                            const float* __restrict__ W1, const float* __restrict__ b1)
{
    __shared__ float As[16][68];   // [k][m], padded
    __shared__ float Ws[16][64];   // [k][n]
    const int tid = threadIdx.x;
    const int bm = blockIdx.y, bn = blockIdx.x;
    const int row0 = bm * 64;
    const bool is_enc = row0 < kEncRows;
    const float* in = is_enc ? (enc + row0 * kD) : (dec + (row0 - kEncRows) * kD);
    const float* W  = is_enc ? W1 : (W1 + kD * kInner);
    const int tx = tid & 15, ty = tid >> 4;

    float acc[4][4];
#pragma unroll
    for (int i = 0; i < 4; i++)
#pragma unroll
        for (int j = 0; j < 4; j++) acc[i][j] = 0.f;

    for (int kt = 0; kt < kD / 16; kt++) {
        float4 av = *(const float4*)(in + (tid >> 2) * kD + kt * 16 + (tid & 3) * 4);
        float4 wv = *(const float4*)(W + (kt * 16 + (tid >> 4)) * kInner + bn * 64 + (tid & 15) * 4);
        As[(tid & 3) * 4 + 0][tid >> 2] = av.x;
        As[(tid & 3) * 4 + 1][tid >> 2] = av.y;
        As[(tid & 3) * 4 + 2][tid >> 2] = av.z;
        As[(tid & 3) * 4 + 3][tid >> 2] = av.w;
        *(float4*)&Ws[tid >> 4][(tid & 15) * 4] = wv;
        __syncthreads();
#pragma unroll
        for (int k = 0; k < 16; k++) {
            float ar[4], br[4];
#pragma unroll
            for (int i = 0; i < 4; i++) ar[i] = As[k][ty * 4 + i];
#pragma unroll
            for (int j = 0; j < 4; j++) br[j] = Ws[k][tx * 4 + j];
#pragma unroll
            for (int i = 0; i < 4; i++)
#pragma unroll
                for (int j = 0; j < 4; j++) acc[i][j] += ar[i] * br[j];
        }
        __syncthreads();
    }

    float* outp = is_enc ? g_eproj : g_dproj;
    const int obase = is_enc ? row0 : (row0 - kEncRows);
#pragma unroll
    for (int i = 0; i < 4; i++) {
        const int row = obase + ty * 4 + i;
#pragma unroll
        for (int j = 0; j < 4; j++) {
            const int n = bn * 64 + tx * 4 + j;
            float v = acc[i][j];
            if (is_enc) v += b1[n];           // fold bias into enc projection
            outp[row * kInner + n] = v;
        }
    }
}

// ---------------------------------------------------------------------------
// K2: hidden = tanh(eproj[b,t] + dproj[b,u])  (b1 already folded into eproj)
// Saturating cheap tanh via MUFU ex2/rcp; accurate to ~1e-6 rel, no NaN at inf.
// ---------------------------------------------------------------------------
__device__ __forceinline__ float fast_tanh(float x) {
    float e = __expf(2.0f * x);
    return 1.0f - __fdividef(2.0f, e + 1.0f);
}

__global__ void hidden_kernel()
{
    const int idx = blockIdx.x * blockDim.x + threadIdx.x;  // float4 index
    const int r = idx >> 7;                // row in [0, 65536): ((b*T+t)*U+u)
    const int c4 = idx & 127;
    const int erow = r >> 6;               // b*T + t
    const int drow = ((r >> 14) << 6) | (r & 63);  // b*U + u
    const float4 e = *(const float4*)(g_eproj + erow * kInner + c4 * 4);
    const float4 d = *(const float4*)(g_dproj + drow * kInner + c4 * 4);
    float4 h;
    h.x = fast_tanh(e.x + d.x);
    h.y = fast_tanh(e.y + d.y);
    h.z = fast_tanh(e.z + d.z);
    h.w = fast_tanh(e.w + d.w);
    *(float4*)(g_hidden + (size_t)idx * 4) = h;
}

// ---------------------------------------------------------------------------
// K3: logits = hidden(65536x512) @ W2(512x2048) + b2, tf32 mma.sync.
// BM=128 BN=128 BK=16, 256 threads, 8 warps (2x4), warp tile 64x32.
// A smem: [m][k] stride 20 (conflict-free frag loads). B smem: n XOR (8k).
// ---------------------------------------------------------------------------
__device__ __forceinline__ unsigned f2tf(float x) {
    unsigned r;
    asm("cvt.rna.tf32.f32 %0, %1;" : "=r"(r) : "f"(x));
    return r;
}

__device__ __forceinline__ void mma_tf32(float* c, const unsigned* a, const unsigned* b) {
    asm volatile(
        "mma.sync.aligned.m16n8k8.row.col.f32.tf32.tf32.f32 "
        "{%0,%1,%2,%3}, {%4,%5,%6,%7}, {%8,%9}, {%0,%1,%2,%3};\n"
        : "+f"(c[0]), "+f"(c[1]), "+f"(c[2]), "+f"(c[3])
        : "r"(a[0]), "r"(a[1]), "r"(a[2]), "r"(a[3]), "r"(b[0]), "r"(b[1]));
}

__global__ __launch_bounds__(256, 2)
void joint_gemm_kernel(const float* __restrict__ W2, const float* __restrict__ b2,
                       float* __restrict__ out)
{
    __shared__ unsigned As[2][128][20];      // [buf][m][k] (BK=16 + pad 4)
    __shared__ unsigned Bs2[2][16 * 128];    // [buf][k*128 + (n ^ 8k)]

    const int tid = threadIdx.x;
    const int lane = tid & 31;
    const int warp = tid >> 5;
    const int wm = warp >> 2, wn = warp & 3;
    const int g = lane >> 2, l = lane & 3;
    const int bm = blockIdx.y, bn = blockIdx.x;

    const float* Ap = g_hidden + (size_t)bm * 128 * kInner + (tid >> 2) * kInner + (tid & 3) * 4;
    const float* Bp = W2 + (tid >> 5) * kVocab + bn * 128 + (tid & 31) * 4;

    float acc[4][4][4];
#pragma unroll
    for (int mt = 0; mt < 4; mt++)
#pragma unroll
        for (int nt = 0; nt < 4; nt++)
#pragma unroll
            for (int i = 0; i < 4; i++) acc[mt][nt][i] = 0.f;

    const int arow = tid >> 2, ak = (tid & 3) * 4;
    const int bk = tid >> 5, bn0 = (tid & 31) * 4;

    float4 ta0, ta1, tb0, tb1;
    // prefetch kt = 0
    ta0 = *(const float4*)(Ap);
    ta1 = *(const float4*)(Ap + 64 * kInner);
    tb0 = *(const float4*)(Bp);
    tb1 = *(const float4*)(Bp + 8 * kVocab);

    // stage tile 0 (convert fp32 -> tf32 at store)
    {
        As[0][arow][ak + 0] = f2tf(ta0.x);
        As[0][arow][ak + 1] = f2tf(ta0.y);
        As[0][arow][ak + 2] = f2tf(ta0.z);
        As[0][arow][ak + 3] = f2tf(ta0.w);
        As[0][arow + 64][ak + 0] = f2tf(ta1.x);
        As[0][arow + 64][ak + 1] = f2tf(ta1.y);
        As[0][arow + 64][ak + 2] = f2tf(ta1.z);
        As[0][arow + 64][ak + 3] = f2tf(ta1.w);
        unsigned* d0 = &Bs2[0][bk * 128 + (bn0 ^ (bk * 8))];
        d0[0] = f2tf(tb0.x); d0[1] = f2tf(tb0.y); d0[2] = f2tf(tb0.z); d0[3] = f2tf(tb0.w);
        unsigned* d1 = &Bs2[0][(bk + 8) * 128 + (bn0 ^ ((bk + 8) * 8))];
        d1[0] = f2tf(tb1.x); d1[1] = f2tf(tb1.y); d1[2] = f2tf(tb1.z); d1[3] = f2tf(tb1.w);
    }
    __syncthreads();

    int buf = 0;
    for (int kt = 0; kt < kInner / 16; kt++) {
        if (kt < kInner / 16 - 1) {
            const float* Ap2 = Ap + (kt + 1) * 16;
            ta0 = *(const float4*)(Ap2);
            ta1 = *(const float4*)(Ap2 + 64 * kInner);
            const float* Bp2 = Bp + (size_t)(kt + 1) * 16 * kVocab;
            tb0 = *(const float4*)(Bp2);
            tb1 = *(const float4*)(Bp2 + 8 * kVocab);
        }
#pragma unroll
        for (int ks = 0; ks < 2; ks++) {
            const int k0 = ks * 8;
            unsigned afr[4][4], bfr[4][2];
#pragma unroll
            for (int mt = 0; mt < 4; mt++) {
                const int m0 = wm * 64 + mt * 16 + g;
                afr[mt][0] = As[buf][m0][k0 + l];
                afr[mt][1] = As[buf][m0 + 8][k0 + l];
                afr[mt][2] = As[buf][m0][k0 + 4 + l];
                afr[mt][3] = As[buf][m0 + 8][k0 + 4 + l];
            }
            const int kk = k0 + l, kk2 = kk + 4;
#pragma unroll
            for (int nt = 0; nt < 4; nt++) {
                const int n = wn * 32 + nt * 8 + g;
                bfr[nt][0] = Bs2[buf][kk * 128 + (n ^ (kk * 8))];
                bfr[nt][1] = Bs2[buf][kk2 * 128 + (n ^ (kk2 * 8))];
            }
#pragma unroll
            for (int mt = 0; mt < 4; mt++)
#pragma unroll
                for (int nt = 0; nt < 4; nt++)
                    mma_tf32(acc[mt][nt], afr[mt], bfr[nt]);
        }
        if (kt < kInner / 16 - 1) {
            const int nb = buf ^ 1;
            As[nb][arow][ak + 0] = f2tf(ta0.x);
            As[nb][arow][ak + 1] = f2tf(ta0.y);
            As[nb][arow][ak + 2] = f2tf(ta0.z);
            As[nb][arow][ak + 3] = f2tf(ta0.w);
            As[nb][arow + 64][ak + 0] = f2tf(ta1.x);
            As[nb][arow + 64][ak + 1] = f2tf(ta1.y);
            As[nb][arow + 64][ak + 2] = f2tf(ta1.z);
            As[nb][arow + 64][ak + 3] = f2tf(ta1.w);
            unsigned* d0 = &Bs2[nb][bk * 128 + (bn0 ^ (bk * 8))];
            d0[0] = f2tf(tb0.x); d0[1] = f2tf(tb0.y); d0[2] = f2tf(tb0.z); d0[3] = f2tf(tb0.w);
            unsigned* d1 = &Bs2[nb][(bk + 8) * 128 + (bn0 ^ ((bk + 8) * 8))];
            d1[0] = f2tf(tb1.x); d1[1] = f2tf(tb1.y); d1[2] = f2tf(tb1.z); d1[3] = f2tf(tb1.w);
            __syncthreads();
            buf = nb;
        }
    }

    // epilogue: add b2, write fp32 logits (fully covers d_out)
    const int rbase = bm * 128 + wm * 64;
    const int cbase = bn * 128 + wn * 32;
#pragma unroll
    for (int mt = 0; mt < 4; mt++) {
#pragma unroll
        for (int nt = 0; nt < 4; nt++) {
            const int r0 = rbase + mt * 16 + g;
            const int c0 = cbase + nt * 8 + l * 2;
            const float2 bb = *(const float2*)(b2 + c0);
            float2 v0 = make_float2(acc[mt][nt][0] + bb.x, acc[mt][nt][1] + bb.y);
            float2 v1 = make_float2(acc[mt][nt][2] + bb.x, acc[mt][nt][3] + bb.y);
            *(float2*)(out + (size_t)r0 * kVocab + c0) = v0;
            *(float2*)(out + (size_t)(r0 + 8) * kVocab + c0) = v1;
        }
    }
}

// ---------------------------------------------------------------------------
extern "C" void kernel_launch(void* const* d_in, const int* in_sizes, int n_in,
                              void* d_out, int out_size)
{
    const float* enc = (const float*)d_in[0];
    const float* dec = (const float*)d_in[1];
    const float* W1  = (const float*)d_in[2];
    const float* b1  = (const float*)d_in[3];
    const float* W2  = (const float*)d_in[4];
    const float* b2  = (const float*)d_in[5];
    float* out = (float*)d_out;

    proj_kernel<<<dim3(kInner / 64, (kEncRows + kDecRows) / 64), 256>>>(enc, dec, W1, b1);
    hidden_kernel<<<(kMRows * (kInner / 4)) / 256, 256>>>();
    joint_gemm_kernel<<<dim3(kVocab / 128, kMRows / 128), 256>>>(W2, b2, out);
}

// round 3
// speedup vs baseline: 1.0006x; 1.0006x over previous
#include <cuda_runtime.h>

// Problem constants
constexpr int kB = 4, kT = 256, kU = 64, kD = 512, kInner = 512, kVocab = 2048;
constexpr int kEncRows = kB * kT;      // 1024
constexpr int kDecRows = kB * kU;      // 256
constexpr int kMRows   = kB * kT * kU; // 65536

// Scratch (static device globals — allocation-free per harness rules)
__device__ float g_eproj[kEncRows * kInner];                 // enc @ We + b1
__device__ float g_dproj[kDecRows * kInner];                 // dec @ Wd
__device__ float g_hidden[(size_t)kMRows * kInner];          // 134 MB tanh(...)

// ---------------------------------------------------------------------------
// K1: fused projection GEMM. Rows [0,1024) = enc @ W1[:512] + b1,
//     rows [1024,1280) = dec @ W1[512:]. 64x64 tiles, 256 threads, 4x4/thread.
// ---------------------------------------------------------------------------
__global__ void proj_kernel(const float* __restrict__ enc, const float* __restrict__ dec,
                            const float* __restrict__ W1, const float* __restrict__ b1)
{
    __shared__ float As[16][68];   // [k][m], padded
    __shared__ float Ws[16][64];   // [k][n]
    const int tid = threadIdx.x;
    const int bm = blockIdx.y, bn = blockIdx.x;
    const int row0 = bm * 64;
    const bool is_enc = row0 < kEncRows;
    const float* in = is_enc ? (enc + row0 * kD) : (dec + (row0 - kEncRows) * kD);
    const float* W  = is_enc ? W1 : (W1 + kD * kInner);
    const int tx = tid & 15, ty = tid >> 4;

    float acc[4][4];
#pragma unroll
    for (int i = 0; i < 4; i++)
#pragma unroll
        for (int j = 0; j < 4; j++) acc[i][j] = 0.f;

    for (int kt = 0; kt < kD / 16; kt++) {
        float4 av = *(const float4*)(in + (tid >> 2) * kD + kt * 16 + (tid & 3) * 4);
        float4 wv = *(const float4*)(W + (kt * 16 + (tid >> 4)) * kInner + bn * 64 + (tid & 15) * 4);
        As[(tid & 3) * 4 + 0][tid >> 2] = av.x;
        As[(tid & 3) * 4 + 1][tid >> 2] = av.y;
        As[(tid & 3) * 4 + 2][tid >> 2] = av.z;
        As[(tid & 3) * 4 + 3][tid >> 2] = av.w;
        *(float4*)&Ws[tid >> 4][(tid & 15) * 4] = wv;
        __syncthreads();
#pragma unroll
        for (int k = 0; k < 16; k++) {
            float ar[4], br[4];
#pragma unroll
            for (int i = 0; i < 4; i++) ar[i] = As[k][ty * 4 + i];
#pragma unroll
            for (int j = 0; j < 4; j++) br[j] = Ws[k][tx * 4 + j];
#pragma unroll
            for (int i = 0; i < 4; i++)
#pragma unroll
                for (int j = 0; j < 4; j++) acc[i][j] += ar[i] * br[j];
        }
        __syncthreads();
    }

    float* outp = is_enc ? g_eproj : g_dproj;
    const int obase = is_enc ? row0 : (row0 - kEncRows);
#pragma unroll
    for (int i = 0; i < 4; i++) {
        const int row = obase + ty * 4 + i;
#pragma unroll
        for (int j = 0; j < 4; j++) {
            const int n = bn * 64 + tx * 4 + j;
            float v = acc[i][j];
            if (is_enc) v += b1[n];           // fold bias into enc projection
            outp[row * kInner + n] = v;
        }
    }
}

// ---------------------------------------------------------------------------
// K2: hidden = tanh(eproj[b,t] + dproj[b,u])  (b1 already folded into eproj)
// Saturating cheap tanh via MUFU ex2/rcp; accurate to ~1e-6 rel, no NaN at inf.
// ---------------------------------------------------------------------------
__device__ __forceinline__ float fast_tanh(float x) {
    float e = __expf(2.0f * x);
    return 1.0f - __fdividef(2.0f, e + 1.0f);
}

__global__ void hidden_kernel()
{
    const int idx = blockIdx.x * blockDim.x + threadIdx.x;  // float4 index
    const int r = idx >> 7;                // row in [0, 65536): ((b*T+t)*U+u)
    const int c4 = idx & 127;
    const int erow = r >> 6;               // b*T + t
    const int drow = ((r >> 14) << 6) | (r & 63);  // b*U + u
    const float4 e = *(const float4*)(g_eproj + erow * kInner + c4 * 4);
    const float4 d = *(const float4*)(g_dproj + drow * kInner + c4 * 4);
    float4 h;
    h.x = fast_tanh(e.x + d.x);
    h.y = fast_tanh(e.y + d.y);
    h.z = fast_tanh(e.z + d.z);
    h.w = fast_tanh(e.w + d.w);
    *(float4*)(g_hidden + (size_t)idx * 4) = h;
}

// ---------------------------------------------------------------------------
// K3: logits = hidden(65536x512) @ W2(512x2048) + b2, tf32 mma.sync.
// BM=128 BN=128 BK=16, 256 threads, 8 warps (2x4), warp tile 64x32.
// A smem: [m][k] stride 20 (conflict-free frag loads). B smem: n XOR (8k).
// ---------------------------------------------------------------------------
__device__ __forceinline__ unsigned f2tf(float x) {
    unsigned r;
    asm("cvt.rna.tf32.f32 %0, %1;" : "=r"(r) : "f"(x));
    return r;
}

__device__ __forceinline__ void mma_tf32(float* c, const unsigned* a, const unsigned* b) {
    asm volatile(
        "mma.sync.aligned.m16n8k8.row.col.f32.tf32.tf32.f32 "
        "{%0,%1,%2,%3}, {%4,%5,%6,%7}, {%8,%9}, {%0,%1,%2,%3};\n"
        : "+f"(c[0]), "+f"(c[1]), "+f"(c[2]), "+f"(c[3])
        : "r"(a[0]), "r"(a[1]), "r"(a[2]), "r"(a[3]), "r"(b[0]), "r"(b[1]));
}

__global__ __launch_bounds__(256, 2)
void joint_gemm_kernel(const float* __restrict__ W2, const float* __restrict__ b2,
                       float* __restrict__ out)
{
    __shared__ unsigned As[2][128][20];      // [buf][m][k] (BK=16 + pad 4)
    __shared__ unsigned Bs2[2][16 * 128];    // [buf][k*128 + (n ^ 8k)]

    const int tid = threadIdx.x;
    const int lane = tid & 31;
    const int warp = tid >> 5;
    const int wm = warp >> 2, wn = warp & 3;
    const int g = lane >> 2, l = lane & 3;
    const int bm = blockIdx.y, bn = blockIdx.x;

    const float* Ap = g_hidden + (size_t)bm * 128 * kInner + (tid >> 2) * kInner + (tid & 3) * 4;
    const float* Bp = W2 + (tid >> 5) * kVocab + bn * 128 + (tid & 31) * 4;

    float acc[4][4][4];
#pragma unroll
    for (int mt = 0; mt < 4; mt++)
#pragma unroll
        for (int nt = 0; nt < 4; nt++)
#pragma unroll
            for (int i = 0; i < 4; i++) acc[mt][nt][i] = 0.f;

    const int arow = tid >> 2, ak = (tid & 3) * 4;
    const int bk = tid >> 5, bn0 = (tid & 31) * 4;

    float4 ta0, ta1, tb0, tb1;
    // prefetch kt = 0
    ta0 = *(const float4*)(Ap);
    ta1 = *(const float4*)(Ap + 64 * kInner);
    tb0 = *(const float4*)(Bp);
    tb1 = *(const float4*)(Bp + 8 * kVocab);

    // stage tile 0 (convert fp32 -> tf32 at store)
    {
        As[0][arow][ak + 0] = f2tf(ta0.x);
        As[0][arow][ak + 1] = f2tf(ta0.y);
        As[0][arow][ak + 2] = f2tf(ta0.z);
        As[0][arow][ak + 3] = f2tf(ta0.w);
        As[0][arow + 64][ak + 0] = f2tf(ta1.x);
        As[0][arow + 64][ak + 1] = f2tf(ta1.y);
        As[0][arow + 64][ak + 2] = f2tf(ta1.z);
        As[0][arow + 64][ak + 3] = f2tf(ta1.w);
        unsigned* d0 = &Bs2[0][bk * 128 + (bn0 ^ (bk * 8))];
        d0[0] = f2tf(tb0.x); d0[1] = f2tf(tb0.y); d0[2] = f2tf(tb0.z); d0[3] = f2tf(tb0.w);
        unsigned* d1 = &Bs2[0][(bk + 8) * 128 + (bn0 ^ ((bk + 8) * 8))];
        d1[0] = f2tf(tb1.x); d1[1] = f2tf(tb1.y); d1[2] = f2tf(tb1.z); d1[3] = f2tf(tb1.w);
    }
    __syncthreads();

    int buf = 0;
    for (int kt = 0; kt < kInner / 16; kt++) {
        if (kt < kInner / 16 - 1) {
            const float* Ap2 = Ap + (kt + 1) * 16;
            ta0 = *(const float4*)(Ap2);
            ta1 = *(const float4*)(Ap2 + 64 * kInner);
            const float* Bp2 = Bp + (size_t)(kt + 1) * 16 * kVocab;
            tb0 = *(const float4*)(Bp2);
            tb1 = *(const float4*)(Bp2 + 8 * kVocab);
        }
#pragma unroll
        for (int ks = 0; ks < 2; ks++) {
            const int k0 = ks * 8;
            unsigned afr[4][4], bfr[4][2];
#pragma unroll
            for (int mt = 0; mt < 4; mt++) {
                const int m0 = wm * 64 + mt * 16 + g;
                afr[mt][0] = As[buf][m0][k0 + l];
                afr[mt][1] = As[buf][m0 + 8][k0 + l];
                afr[mt][2] = As[buf][m0][k0 + 4 + l];
                afr[mt][3] = As[buf][m0 + 8][k0 + 4 + l];
            }
            const int kk = k0 + l, kk2 = kk + 4;
#pragma unroll
            for (int nt = 0; nt < 4; nt++) {
                const int n = wn * 32 + nt * 8 + g;
                bfr[nt][0] = Bs2[buf][kk * 128 + (n ^ (kk * 8))];
                bfr[nt][1] = Bs2[buf][kk2 * 128 + (n ^ (kk2 * 8))];
            }
#pragma unroll
            for (int mt = 0; mt < 4; mt++)
#pragma unroll
                for (int nt = 0; nt < 4; nt++)
                    mma_tf32(acc[mt][nt], afr[mt], bfr[nt]);
        }
        if (kt < kInner / 16 - 1) {
            const int nb = buf ^ 1;
            As[nb][arow][ak + 0] = f2tf(ta0.x);
            As[nb][arow][ak + 1] = f2tf(ta0.y);
            As[nb][arow][ak + 2] = f2tf(ta0.z);
            As[nb][arow][ak + 3] = f2tf(ta0.w);
            As[nb][arow + 64][ak + 0] = f2tf(ta1.x);
            As[nb][arow + 64][ak + 1] = f2tf(ta1.y);
            As[nb][arow + 64][ak + 2] = f2tf(ta1.z);
            As[nb][arow + 64][ak + 3] = f2tf(ta1.w);
            unsigned* d0 = &Bs2[nb][bk * 128 + (bn0 ^ (bk * 8))];
            d0[0] = f2tf(tb0.x); d0[1] = f2tf(tb0.y); d0[2] = f2tf(tb0.z); d0[3] = f2tf(tb0.w);
            unsigned* d1 = &Bs2[nb][(bk + 8) * 128 + (bn0 ^ ((bk + 8) * 8))];
            d1[0] = f2tf(tb1.x); d1[1] = f2tf(tb1.y); d1[2] = f2tf(tb1.z); d1[3] = f2tf(tb1.w);
            __syncthreads();
            buf = nb;
        }
    }

    // epilogue: add b2, write fp32 logits (fully covers d_out)
    const int rbase = bm * 128 + wm * 64;
    const int cbase = bn * 128 + wn * 32;
#pragma unroll
    for (int mt = 0; mt < 4; mt++) {
#pragma unroll
        for (int nt = 0; nt < 4; nt++) {
            const int r0 = rbase + mt * 16 + g;
            const int c0 = cbase + nt * 8 + l * 2;
            const float2 bb = *(const float2*)(b2 + c0);
            float2 v0 = make_float2(acc[mt][nt][0] + bb.x, acc[mt][nt][1] + bb.y);
            float2 v1 = make_float2(acc[mt][nt][2] + bb.x, acc[mt][nt][3] + bb.y);
            *(float2*)(out + (size_t)r0 * kVocab + c0) = v0;
            *(float2*)(out + (size_t)(r0 + 8) * kVocab + c0) = v1;
        }
    }
}

// ---------------------------------------------------------------------------
extern "C" void kernel_launch(void* const* d_in, const int* in_sizes, int n_in,
                              void* d_out, int out_size)
{
    const float* enc = (const float*)d_in[0];
    const float* dec = (const float*)d_in[1];
    const float* W1  = (const float*)d_in[2];
    const float* b1  = (const float*)d_in[3];
    const float* W2  = (const float*)d_in[4];
    const float* b2  = (const float*)d_in[5];
    float* out = (float*)d_out;

    proj_kernel<<<dim3(kInner / 64, (kEncRows + kDecRows) / 64), 256>>>(enc, dec, W1, b1);
    hidden_kernel<<<(kMRows * (kInner / 4)) / 256, 256>>>();
    joint_gemm_kernel<<<dim3(kVocab / 128, kMRows / 128), 256>>>(W2, b2, out);
}

// round 5
// speedup vs baseline: 1.5202x; 1.5193x over previous
#include <cuda_runtime.h>
#include <cuda_fp16.h>
#include <cstdint>

constexpr int kD = 512, kInner = 512, kVocab = 2048;
constexpr int kEncRows = 1024, kDecRows = 256, kMRows = 65536;

__device__ float g_eproj[kEncRows * kInner];   // enc @ We + b1
__device__ float g_dproj[kDecRows * kInner];   // dec @ Wd
__device__ __half g_w2h[(size_t)kVocab * kInner];  // W2^T as fp16, [v][k]

// ---------------- helpers ----------------
__device__ __forceinline__ uint32_t smem_u32(const void* p) {
    uint32_t a;
    asm("{ .reg .u64 t; cvta.to.shared.u64 t, %1; cvt.u32.u64 %0, t; }" : "=r"(a) : "l"(p));
    return a;
}
#define CP_COMMIT() asm volatile("cp.async.commit_group;" ::: "memory")
#define CP_WAIT0()  asm volatile("cp.async.wait_group 0;" ::: "memory")
__device__ __forceinline__ void cpasync16(uint32_t dst, const void* src) {
    asm volatile("cp.async.cg.shared.global [%0], [%1], 16;" :: "r"(dst), "l"(src) : "memory");
}
#define LDSM_X4(r0, r1, r2, r3, a) \
    asm volatile("ldmatrix.sync.aligned.m8n8.x4.shared.b16 {%0,%1,%2,%3}, [%4];" \
                 : "=r"(r0), "=r"(r1), "=r"(r2), "=r"(r3) : "r"(a))
__device__ __forceinline__ void mma16816(float* c, const uint32_t* a, const uint32_t* b) {
    asm volatile("mma.sync.aligned.m16n8k16.row.col.f32.f16.f16.f32 "
                 "{%0,%1,%2,%3}, {%4,%5,%6,%7}, {%8,%9}, {%0,%1,%2,%3};"
                 : "+f"(c[0]), "+f"(c[1]), "+f"(c[2]), "+f"(c[3])
                 : "r"(a[0]), "r"(a[1]), "r"(a[2]), "r"(a[3]), "r"(b[0]), "r"(b[1]));
}
__device__ __forceinline__ void sts128(uint32_t a, uint32_t x, uint32_t y, uint32_t z, uint32_t w) {
    asm volatile("st.shared.v4.b32 [%0], {%1,%2,%3,%4};" :: "r"(a), "r"(x), "r"(y), "r"(z), "r"(w) : "memory");
}
// proven tanh (2 MUFU): same formulation that measured rel_err 2.85e-4
__device__ __forceinline__ float fast_tanh(float x) {
    float e = __expf(2.0f * x);
    return 1.0f - __fdividef(2.0f, e + 1.0f);
}
__device__ __forceinline__ uint32_t pack_h2(float lo, float hi) {
    uint32_t r;
    asm("cvt.rn.f16x2.f32 %0, %1, %2;" : "=r"(r) : "f"(hi), "f"(lo));
    return r;
}

// ---------------- K1: projections (unchanged, known-good) ----------------
__global__ void proj_kernel(const float* __restrict__ enc, const float* __restrict__ dec,
                            const float* __restrict__ W1, const float* __restrict__ b1)
{
    __shared__ float As[16][68];
    __shared__ float Ws[16][64];
    const int tid = threadIdx.x;
    const int bm = blockIdx.y, bn = blockIdx.x;
    const int row0 = bm * 64;
    const bool is_enc = row0 < kEncRows;
    const float* in = is_enc ? (enc + row0 * kD) : (dec + (row0 - kEncRows) * kD);
    const float* W  = is_enc ? W1 : (W1 + kD * kInner);
    const int tx = tid & 15, ty = tid >> 4;

    float acc[4][4];
#pragma unroll
    for (int i = 0; i < 4; i++)
#pragma unroll
        for (int j = 0; j < 4; j++) acc[i][j] = 0.f;

    for (int kt = 0; kt < kD / 16; kt++) {
        float4 av = *(const float4*)(in + (tid >> 2) * kD + kt * 16 + (tid & 3) * 4);
        float4 wv = *(const float4*)(W + (kt * 16 + (tid >> 4)) * kInner + bn * 64 + (tid & 15) * 4);
        As[(tid & 3) * 4 + 0][tid >> 2] = av.x;
        As[(tid & 3) * 4 + 1][tid >> 2] = av.y;
        As[(tid & 3) * 4 + 2][tid >> 2] = av.z;
        As[(tid & 3) * 4 + 3][tid >> 2] = av.w;
        *(float4*)&Ws[tid >> 4][(tid & 15) * 4] = wv;
        __syncthreads();
#pragma unroll
        for (int k = 0; k < 16; k++) {
            float ar[4], br[4];
#pragma unroll
            for (int i = 0; i < 4; i++) ar[i] = As[k][ty * 4 + i];
#pragma unroll
            for (int j = 0; j < 4; j++) br[j] = Ws[k][tx * 4 + j];
#pragma unroll
            for (int i = 0; i < 4; i++)
#pragma unroll
                for (int j = 0; j < 4; j++) acc[i][j] += ar[i] * br[j];
        }
        __syncthreads();
    }
    float* outp = is_enc ? g_eproj : g_dproj;
    const int obase = is_enc ? row0 : (row0 - kEncRows);
#pragma unroll
    for (int i = 0; i < 4; i++)
#pragma unroll
        for (int j = 0; j < 4; j++) {
            const int n = bn * 64 + tx * 4 + j;
            float v = acc[i][j];
            if (is_enc) v += b1[n];
            outp[(obase + ty * 4 + i) * kInner + n] = v;
        }
}

// ---------------- K2: W2 -> fp16 transpose [v][k] ----------------
__global__ void w2h_kernel(const float* __restrict__ W2)
{
    __shared__ float tile[32][33];
    const int tx = threadIdx.x & 31, ty = threadIdx.x >> 5;
    const int v0 = blockIdx.x * 32, k0 = blockIdx.y * 32;
#pragma unroll
    for (int i = 0; i < 4; i++)
        tile[ty + i * 8][tx] = W2[(size_t)(k0 + ty + i * 8) * kVocab + v0 + tx];
    __syncthreads();
#pragma unroll
    for (int i = 0; i < 4; i++)
        g_w2h[(size_t)(v0 + ty + i * 8) * kInner + k0 + tx] = __float2half_rn(tile[tx][ty + i * 8]);
}

// ---------------- K3: fused tanh + fp16 mma.sync GEMM ----------------
// BM=128, BN=256, BK=64, 512 threads (16 warps, 2x8), warp tile 64x32.
// Smem rows: 64 fp16 = 128B, 16B-chunk XOR swizzle (c ^ (row&7)).
constexpr int SMA = 0;            // A: 2 x 128 x 128B = 32KB
constexpr int SMB = 32768;        // B: 2 x 256 x 128B = 64KB
constexpr int SMEM_TOTAL = 98304;

__global__ __launch_bounds__(512, 1)
void fused_joint_kernel(const float* __restrict__ b2, float* __restrict__ out)
{
    extern __shared__ char smem[];
    const uint32_t sb = smem_u32(smem);
    const int tid = threadIdx.x;
    const int lane = tid & 31, wid = tid >> 5;
    const int wm = wid >> 3, wn = wid & 7;
    const int bn = blockIdx.x, bmp = blockIdx.y;

    // A producer mapping: 4 threads/row, 16 k-elems each
    const int arow = tid >> 2, apart = tid & 3;
    const int gm = bmp * 128 + arow;
    const float* ep = g_eproj + (size_t)(gm >> 6) * kInner + apart * 16;
    const float* dp = g_dproj + (size_t)(((gm >> 14) << 6) | (gm & 63)) * kInner + apart * 16;
    const uint32_t a_sts = sb + SMA + arow * 128;
    const int ar7 = arow & 7;
    // B producer mapping: 2 threads/row, 4 x 16B chunks each
    const int brow = tid >> 1;
    const __half* wp = g_w2h + (size_t)(bn * 256 + brow) * kInner + (tid & 1) * 32;
    const uint32_t b_sts = sb + SMB + brow * 128;
    const int br7 = brow & 7;

    float acc[4][4][4];
#pragma unroll
    for (int mt = 0; mt < 4; mt++)
#pragma unroll
        for (int nt = 0; nt < 4; nt++)
#pragma unroll
            for (int i = 0; i < 4; i++) acc[mt][nt][i] = 0.f;

#define PRODUCE_B(kt, buf) do { \
    const uint32_t bb_ = b_sts + (buf) * 32768; \
    _Pragma("unroll") \
    for (int j = 0; j < 4; j++) { \
        const int c_ = (tid & 1) * 4 + j; \
        cpasync16(bb_ + ((c_ ^ br7) * 16), wp + (kt) * 64 + j * 8); \
    } } while (0)

#define PRODUCE_A(kt, buf) do { \
    const uint32_t ab_ = a_sts + (buf) * 16384; \
    _Pragma("unroll") \
    for (int j = 0; j < 2; j++) { \
        float4 e0 = *(const float4*)(ep + (kt) * 64 + j * 8); \
        float4 e1 = *(const float4*)(ep + (kt) * 64 + j * 8 + 4); \
        float4 d0 = *(const float4*)(dp + (kt) * 64 + j * 8); \
        float4 d1 = *(const float4*)(dp + (kt) * 64 + j * 8 + 4); \
        uint32_t h0 = pack_h2(fast_tanh(e0.x + d0.x), fast_tanh(e0.y + d0.y)); \
        uint32_t h1 = pack_h2(fast_tanh(e0.z + d0.z), fast_tanh(e0.w + d0.w)); \
        uint32_t h2 = pack_h2(fast_tanh(e1.x + d1.x), fast_tanh(e1.y + d1.y)); \
        uint32_t h3 = pack_h2(fast_tanh(e1.z + d1.z), fast_tanh(e1.w + d1.w)); \
        const int c_ = apart * 2 + j; \
        sts128(ab_ + ((c_ ^ ar7) * 16), h0, h1, h2, h3); \
    } } while (0)

    // prologue: stage 0
    PRODUCE_B(0, 0);
    CP_COMMIT();
    PRODUCE_A(0, 0);
    CP_WAIT0();
    __syncthreads();

    for (int kt = 0; kt < 8; kt++) {
        const int buf = kt & 1;
        if (kt < 7) {
            PRODUCE_B(kt + 1, buf ^ 1);
            CP_COMMIT();
            PRODUCE_A(kt + 1, buf ^ 1);
        }
        const uint32_t Ab = sb + SMA + buf * 16384;
        const uint32_t Bb = sb + SMB + buf * 32768;
#pragma unroll
        for (int kc = 0; kc < 4; kc++) {
            uint32_t afr[4][4], bfr[4][2];
#pragma unroll
            for (int mt = 0; mt < 4; mt++) {
                const int row = wm * 64 + mt * 16 + (lane & 15);
                const int ch = (kc * 2 + (lane >> 4)) ^ (lane & 7);
                LDSM_X4(afr[mt][0], afr[mt][1], afr[mt][2], afr[mt][3],
                        Ab + row * 128 + ch * 16);
            }
#pragma unroll
            for (int np = 0; np < 2; np++) {
                const int n = wn * 32 + np * 16 + (lane & 7) + ((lane >> 4) << 3);
                const int ch = (kc * 2 + ((lane >> 3) & 1)) ^ (lane & 7);
                LDSM_X4(bfr[np * 2][0], bfr[np * 2][1], bfr[np * 2 + 1][0], bfr[np * 2 + 1][1],
                        Bb + n * 128 + ch * 16);
            }
#pragma unroll
            for (int mt = 0; mt < 4; mt++)
#pragma unroll
                for (int nt = 0; nt < 4; nt++)
                    mma16816(acc[mt][nt], afr[mt], bfr[nt]);
        }
        CP_WAIT0();
        __syncthreads();
    }

    // epilogue: add b2, direct coalesced-sector stores
    const int rbase = bmp * 128 + wm * 64;
    const int cbase = bn * 256 + wn * 32;
    const int g = lane >> 2, l = lane & 3;
#pragma unroll
    for (int nt = 0; nt < 4; nt++) {
        const int c0 = cbase + nt * 8 + l * 2;
        const float2 bb = *(const float2*)(b2 + c0);
#pragma unroll
        for (int mt = 0; mt < 4; mt++) {
            const int r0 = rbase + mt * 16 + g;
            float2 v0 = make_float2(acc[mt][nt][0] + bb.x, acc[mt][nt][1] + bb.y);
            float2 v1 = make_float2(acc[mt][nt][2] + bb.x, acc[mt][nt][3] + bb.y);
            *(float2*)(out + (size_t)r0 * kVocab + c0) = v0;
            *(float2*)(out + (size_t)(r0 + 8) * kVocab + c0) = v1;
        }
    }
}

// ---------------------------------------------------------------------------
extern "C" void kernel_launch(void* const* d_in, const int* in_sizes, int n_in,
                              void* d_out, int out_size)
{
    const float* enc = (const float*)d_in[0];
    const float* dec = (const float*)d_in[1];
    const float* W1  = (const float*)d_in[2];
    const float* b1  = (const float*)d_in[3];
    const float* W2  = (const float*)d_in[4];
    const float* b2  = (const float*)d_in[5];
    float* out = (float*)d_out;

    cudaFuncSetAttribute(fused_joint_kernel,
                         cudaFuncAttributeMaxDynamicSharedMemorySize, SMEM_TOTAL);

    proj_kernel<<<dim3(kInner / 64, (kEncRows + kDecRows) / 64), 256>>>(enc, dec, W1, b1);
    w2h_kernel<<<dim3(kVocab / 32, kInner / 32), 256>>>(W2);
    fused_joint_kernel<<<dim3(kVocab / 256, kMRows / 128), 512, SMEM_TOTAL>>>(b2, out);
}

// round 6
// speedup vs baseline: 1.9051x; 1.2532x over previous
#include <cuda_runtime.h>
#include <cuda_fp16.h>
#include <cstdint>

constexpr int kD = 512, kInner = 512, kVocab = 2048;
constexpr int kEncRows = 1024, kDecRows = 256, kMRows = 65536;

__device__ float g_eproj[kEncRows * kInner];       // enc @ We + b1
__device__ float g_dproj[kDecRows * kInner];       // dec @ Wd
__device__ __half g_w2h[(size_t)kVocab * kInner];  // W2^T as fp16, [v][k]

// ---------------- helpers ----------------
__device__ __forceinline__ uint32_t smem_u32(const void* p) {
    uint32_t a;
    asm("{ .reg .u64 t; cvta.to.shared.u64 t, %1; cvt.u32.u64 %0, t; }" : "=r"(a) : "l"(p));
    return a;
}
#define CP_COMMIT() asm volatile("cp.async.commit_group;" ::: "memory")
#define CP_WAIT0()  asm volatile("cp.async.wait_group 0;" ::: "memory")
__device__ __forceinline__ void cpasync16(uint32_t dst, const void* src) {
    asm volatile("cp.async.cg.shared.global [%0], [%1], 16;" :: "r"(dst), "l"(src) : "memory");
}
#define LDSM_X4(r0, r1, r2, r3, a) \
    asm volatile("ldmatrix.sync.aligned.m8n8.x4.shared.b16 {%0,%1,%2,%3}, [%4];" \
                 : "=r"(r0), "=r"(r1), "=r"(r2), "=r"(r3) : "r"(a))
__device__ __forceinline__ void mma16816(float* c, const uint32_t* a, const uint32_t* b) {
    asm volatile("mma.sync.aligned.m16n8k16.row.col.f32.f16.f16.f32 "
                 "{%0,%1,%2,%3}, {%4,%5,%6,%7}, {%8,%9}, {%0,%1,%2,%3};"
                 : "+f"(c[0]), "+f"(c[1]), "+f"(c[2]), "+f"(c[3])
                 : "r"(a[0]), "r"(a[1]), "r"(a[2]), "r"(a[3]), "r"(b[0]), "r"(b[1]));
}
__device__ __forceinline__ void sts128(uint32_t a, uint32_t x, uint32_t y, uint32_t z, uint32_t w) {
    asm volatile("st.shared.v4.b32 [%0], {%1,%2,%3,%4};" :: "r"(a), "r"(x), "r"(y), "r"(z), "r"(w) : "memory");
}
// proven tanh (same formulation that measured rel_err 2.854e-4)
__device__ __forceinline__ float fast_tanh(float x) {
    float e = __expf(2.0f * x);
    return 1.0f - __fdividef(2.0f, e + 1.0f);
}
__device__ __forceinline__ uint32_t pack_h2(float lo, float hi) {
    uint32_t r;
    asm("cvt.rn.f16x2.f32 %0, %1, %2;" : "=r"(r) : "f"(hi), "f"(lo));
    return r;
}

// ---------------- K1: projections, 32x64 tiles (320 CTAs) ----------------
__global__ void proj_kernel(const float* __restrict__ enc, const float* __restrict__ dec,
                            const float* __restrict__ W1, const float* __restrict__ b1)
{
    __shared__ float As[16][34];   // [k][row], pad 2
    __shared__ float Ws[16][64];
    const int tid = threadIdx.x;
    const int bm = blockIdx.y, bn = blockIdx.x;
    const int row0 = bm * 32;
    const bool is_enc = row0 < kEncRows;
    const float* in = is_enc ? (enc + row0 * kD) : (dec + (row0 - kEncRows) * kD);
    const float* W  = is_enc ? W1 : (W1 + kD * kInner);
    const int tx = tid & 15, ty = tid >> 4;

    float acc[2][4];
#pragma unroll
    for (int i = 0; i < 2; i++)
#pragma unroll
        for (int j = 0; j < 4; j++) acc[i][j] = 0.f;

    for (int kt = 0; kt < kD / 16; kt++) {
        float2 av = *(const float2*)(in + (tid >> 3) * kD + kt * 16 + (tid & 7) * 2);
        float4 wv = *(const float4*)(W + (kt * 16 + (tid >> 4)) * kInner + bn * 64 + (tid & 15) * 4);
        As[(tid & 7) * 2 + 0][tid >> 3] = av.x;
        As[(tid & 7) * 2 + 1][tid >> 3] = av.y;
        *(float4*)&Ws[tid >> 4][(tid & 15) * 4] = wv;
        __syncthreads();
#pragma unroll
        for (int k = 0; k < 16; k++) {
            float ar[2], br[4];
#pragma unroll
            for (int i = 0; i < 2; i++) ar[i] = As[k][ty * 2 + i];
#pragma unroll
            for (int j = 0; j < 4; j++) br[j] = Ws[k][tx * 4 + j];
#pragma unroll
            for (int i = 0; i < 2; i++)
#pragma unroll
                for (int j = 0; j < 4; j++) acc[i][j] += ar[i] * br[j];
        }
        __syncthreads();
    }
    float* outp = is_enc ? g_eproj : g_dproj;
    const int obase = is_enc ? row0 : (row0 - kEncRows);
#pragma unroll
    for (int i = 0; i < 2; i++)
#pragma unroll
        for (int j = 0; j < 4; j++) {
            const int n = bn * 64 + tx * 4 + j;
            float v = acc[i][j];
            if (is_enc) v += b1[n];
            outp[(obase + ty * 2 + i) * kInner + n] = v;
        }
}

// ---------------- K2: W2 -> fp16 transpose [v][k] ----------------
__global__ void w2h_kernel(const float* __restrict__ W2)
{
    __shared__ float tile[32][33];
    const int tx = threadIdx.x & 31, ty = threadIdx.x >> 5;
    const int v0 = blockIdx.x * 32, k0 = blockIdx.y * 32;
#pragma unroll
    for (int i = 0; i < 4; i++)
        tile[ty + i * 8][tx] = W2[(size_t)(k0 + ty + i * 8) * kVocab + v0 + tx];
    __syncthreads();
#pragma unroll
    for (int i = 0; i < 4; i++)
        g_w2h[(size_t)(v0 + ty + i * 8) * kInner + k0 + tx] = __float2half_rn(tile[tx][ty + i * 8]);
}

// ---------------- K3: fused tanh + fp16 mma.sync GEMM, persistent A ----------
// Per CTA: BM=128 rows, FULL K=512 of A resident in smem (8 tiles x 16KB).
// Loop over 8 BN=256 column tiles; B double-buffered (BK=64) via cp.async.
// 512 threads, 16 warps (2x8), warp tile 64x32.
constexpr int SMA = 0;              // A: 8 x 128 x 128B = 128KB
constexpr int SMB = 131072;         // B: 2 x 256 x 128B = 64KB
constexpr int SMEM_TOTAL = 196608;  // 192KB

__global__ __launch_bounds__(512, 1)
void fused_joint_kernel(const float* __restrict__ b2, float* __restrict__ out)
{
    extern __shared__ char smem[];
    const uint32_t sb = smem_u32(smem);
    const int tid = threadIdx.x;
    const int lane = tid & 31, wid = tid >> 5;
    const int wm = wid >> 3, wn = wid & 7;
    const int bmp = blockIdx.x;

    // A producer mapping: 4 threads/row, 16 k-elems each
    const int arow = tid >> 2, apart = tid & 3;
    const int gm = bmp * 128 + arow;
    const float* ep = g_eproj + (size_t)(gm >> 6) * kInner + apart * 16;
    const float* dp = g_dproj + (size_t)(((gm >> 14) << 6) | (gm & 63)) * kInner + apart * 16;
    const uint32_t a_sts = sb + SMA + arow * 128;
    const int ar7 = arow & 7;
    // B producer mapping: 2 threads/row, 4 x 16B chunks each
    const int brow = tid >> 1;
    const __half* wp = g_w2h + (size_t)brow * kInner + (tid & 1) * 32;
    const uint32_t b_sts = sb + SMB + brow * 128;
    const int br7 = brow & 7;

#define PRODUCE_B(s, buf) do { \
    const __half* wps_ = wp + (size_t)((s) >> 3) * 256 * kInner + ((s) & 7) * 64; \
    const uint32_t bb_ = b_sts + (buf) * 32768; \
    _Pragma("unroll") \
    for (int j = 0; j < 4; j++) { \
        const int c_ = (tid & 1) * 4 + j; \
        cpasync16(bb_ + ((c_ ^ br7) * 16), wps_ + j * 8); \
    } } while (0)

    // ---- prologue: stage-0 B load overlapped with full-A tanh production ----
    PRODUCE_B(0, 0);
    CP_COMMIT();
#pragma unroll 1
    for (int kt = 0; kt < 8; kt++) {
        const uint32_t ab_ = a_sts + kt * 16384;
#pragma unroll
        for (int j = 0; j < 2; j++) {
            float4 e0 = *(const float4*)(ep + kt * 64 + j * 8);
            float4 e1 = *(const float4*)(ep + kt * 64 + j * 8 + 4);
            float4 d0 = *(const float4*)(dp + kt * 64 + j * 8);
            float4 d1 = *(const float4*)(dp + kt * 64 + j * 8 + 4);
            uint32_t h0 = pack_h2(fast_tanh(e0.x + d0.x), fast_tanh(e0.y + d0.y));
            uint32_t h1 = pack_h2(fast_tanh(e0.z + d0.z), fast_tanh(e0.w + d0.w));
            uint32_t h2 = pack_h2(fast_tanh(e1.x + d1.x), fast_tanh(e1.y + d1.y));
            uint32_t h3 = pack_h2(fast_tanh(e1.z + d1.z), fast_tanh(e1.w + d1.w));
            const int c_ = apart * 2 + j;
            sts128(ab_ + ((c_ ^ ar7) * 16), h0, h1, h2, h3);
        }
    }
    CP_WAIT0();
    __syncthreads();

    float acc[4][4][4];
#pragma unroll
    for (int mt = 0; mt < 4; mt++)
#pragma unroll
        for (int nt = 0; nt < 4; nt++)
#pragma unroll
            for (int i = 0; i < 4; i++) acc[mt][nt][i] = 0.f;

    const int rbase = bmp * 128 + wm * 64;
    const int g2 = lane >> 2, l2 = lane & 3;

    // ---- mainloop: 64 stages = 8 bn tiles x 8 k-stages ----
#pragma unroll 1
    for (int s = 0; s < 64; s++) {
        const int buf = s & 1;
        if (s < 63) PRODUCE_B(s + 1, buf ^ 1);
        CP_COMMIT();
        const uint32_t Ab = sb + SMA + (s & 7) * 16384;
        const uint32_t Bb = sb + SMB + buf * 32768;
#pragma unroll
        for (int kc = 0; kc < 4; kc++) {
            uint32_t afr[4][4], bfr[4][2];
#pragma unroll
            for (int mt = 0; mt < 4; mt++) {
                const int row = wm * 64 + mt * 16 + (lane & 15);
                const int ch = (kc * 2 + (lane >> 4)) ^ (lane & 7);
                LDSM_X4(afr[mt][0], afr[mt][1], afr[mt][2], afr[mt][3],
                        Ab + row * 128 + ch * 16);
            }
#pragma unroll
            for (int np = 0; np < 2; np++) {
                const int n = wn * 32 + np * 16 + (lane & 7) + ((lane >> 4) << 3);
                const int ch = (kc * 2 + ((lane >> 3) & 1)) ^ (lane & 7);
                LDSM_X4(bfr[np * 2][0], bfr[np * 2][1], bfr[np * 2 + 1][0], bfr[np * 2 + 1][1],
                        Bb + n * 128 + ch * 16);
            }
#pragma unroll
            for (int mt = 0; mt < 4; mt++)
#pragma unroll
                for (int nt = 0; nt < 4; nt++)
                    mma16816(acc[mt][nt], afr[mt], bfr[nt]);
        }
        if ((s & 7) == 7) {
            // finished bn tile: add b2, write out, reset acc
            const int bn = s >> 3;
            const int cbase = bn * 256 + wn * 32;
#pragma unroll
            for (int nt = 0; nt < 4; nt++) {
                const int c0 = cbase + nt * 8 + l2 * 2;
                const float2 bb = *(const float2*)(b2 + c0);
#pragma unroll
                for (int mt = 0; mt < 4; mt++) {
                    const int r0 = rbase + mt * 16 + g2;
                    float2 v0 = make_float2(acc[mt][nt][0] + bb.x, acc[mt][nt][1] + bb.y);
                    float2 v1 = make_float2(acc[mt][nt][2] + bb.x, acc[mt][nt][3] + bb.y);
                    *(float2*)(out + (size_t)r0 * kVocab + c0) = v0;
                    *(float2*)(out + (size_t)(r0 + 8) * kVocab + c0) = v1;
#pragma unroll
                    for (int i = 0; i < 4; i++) acc[mt][nt][i] = 0.f;
                }
            }
        }
        CP_WAIT0();
        __syncthreads();
    }
}

// ---------------------------------------------------------------------------
extern "C" void kernel_launch(void* const* d_in, const int* in_sizes, int n_in,
                              void* d_out, int out_size)
{
    const float* enc = (const float*)d_in[0];
    const float* dec = (const float*)d_in[1];
    const float* W1  = (const float*)d_in[2];
    const float* b1  = (const float*)d_in[3];
    const float* W2  = (const float*)d_in[4];
    const float* b2  = (const float*)d_in[5];
    float* out = (float*)d_out;

    cudaFuncSetAttribute(fused_joint_kernel,
                         cudaFuncAttributeMaxDynamicSharedMemorySize, SMEM_TOTAL);

    proj_kernel<<<dim3(kInner / 64, (kEncRows + kDecRows) / 32), 256>>>(enc, dec, W1, b1);
    w2h_kernel<<<dim3(kVocab / 32, kInner / 32), 256>>>(W2);
    fused_joint_kernel<<<kMRows / 128, 512, SMEM_TOTAL>>>(b2, out);
}